// round 7
// baseline (speedup 1.0000x reference)
#include <cuda_runtime.h>
#include <cuda_fp16.h>
#include <cstdint>
#include <cstddef>

#define C_IN 256
#define HW 128
#define IMG (HW*HW)
#define KC 8              // k2-rows (half2 channel-pairs) per chunk = 16 channels
#define NCHUNK 16
#define AS_H_ST 136       // elements: 4 halo + 128 + 4 halo  (% 32 == 8)
#define AS_V_ST 264       // elements: 16 rows x 16 w + pad    (% 32 == 8)
#define BS_STRIDE 72      // % 32 == 8
#define NTAP 5
#define NGROUP 4

// x converted to half2 channel-pairs: [img][c2(128)][pix]
__device__ uint32_t g_xh[(size_t)16*128*IMG];           // 128 MB
// binarized weights, half2 channel-pairs: [g][t][k2(128)][co(64)]
__device__ uint32_t g_wb[NGROUP*NTAP*128*64];

__global__ void prep_weights(const float* __restrict__ w1, const float* __restrict__ w2,
                             const float* __restrict__ w3, const float* __restrict__ w4) {
    int idx = blockIdx.x * blockDim.x + threadIdx.x;
    if (idx >= NGROUP*NTAP*128*64) return;
    int n   = idx & 63;
    int k2  = (idx >> 6) & 127;
    int gt  = idx >> 13;              // g*5 + t
    int t = gt % 5, g = gt / 5;
    int c0 = 2*k2;
    const float* w = g==0?w1:g==1?w2:g==2?w3:w4;
    float v0 = w[((size_t)n*C_IN + c0    )*NTAP + t];
    float v1 = w[((size_t)n*C_IN + c0 + 1)*NTAP + t];
    uint32_t lo = (v0 < 0.f) ? 0xBC00u : 0x3C00u;     // fp16 -1 / +1
    uint32_t hi = (v1 < 0.f) ? 0xBC00u : 0x3C00u;
    g_wb[idx] = (hi << 16) | lo;
}

__device__ __forceinline__ uint32_t pack_h2(float a, float b) {
    uint32_t r;
    asm("cvt.rn.f16x2.f32 %0, %1, %2;" : "=r"(r) : "f"(b), "f"(a));
    return r;
}

__global__ void convert_x(const float* __restrict__ x) {
    size_t i = (size_t)blockIdx.x * blockDim.x + threadIdx.x;   // uint4 index
    int pix4 = (int)(i & 4095);
    int c2   = (int)((i >> 12) & 127);
    int img  = (int)(i >> 19);
    const float4* p0 = reinterpret_cast<const float4*>(
        x + ((size_t)img*C_IN + 2*c2    )*IMG) + pix4;
    const float4* p1 = reinterpret_cast<const float4*>(
        x + ((size_t)img*C_IN + 2*c2 + 1)*IMG) + pix4;
    float4 a = *p0, b = *p1;
    uint4 o;
    o.x = pack_h2(a.x, b.x);
    o.y = pack_h2(a.y, b.y);
    o.z = pack_h2(a.z, b.z);
    o.w = pack_h2(a.w, b.w);
    reinterpret_cast<uint4*>(g_xh)[i] = o;
}

#define MMA_F16(cd, A0,A1,A2,A3, B0,B1)                                      \
  asm volatile("mma.sync.aligned.m16n8k16.row.col.f32.f16.f16.f32 "          \
    "{%0,%1,%2,%3},{%4,%5,%6,%7},{%8,%9},{%0,%1,%2,%3};\n"                   \
    : "+f"(cd[0]), "+f"(cd[1]), "+f"(cd[2]), "+f"(cd[3])                     \
    : "r"(A0), "r"(A1), "r"(A2), "r"(A3), "r"(B0), "r"(B1))

__device__ __forceinline__ void cp_async16(uint32_t dst, const void* src, int src_bytes) {
    asm volatile("cp.async.cg.shared.global [%0], [%1], 16, %2;\n"
                 :: "r"(dst), "l"(src), "r"(src_bytes));
}
__device__ __forceinline__ void cp_commit()  { asm volatile("cp.async.commit_group;\n"); }
__device__ __forceinline__ void cp_wait0()   { asm volatile("cp.async.wait_group 0;\n"); }

// CTA: M=128 pixels x N=64 co, fp16 MMA. 256 threads = 8 warps (4M x 2N),
// warp tile 32x32 (32 accs/thread -> <=128 regs -> 2 CTAs = 16 warps/SM).
__global__ __launch_bounds__(256, 2) void mrb_conv_kernel(
    const float* __restrict__ bb1, const float* __restrict__ bb2,
    const float* __restrict__ bb3, const float* __restrict__ bb4,
    float* __restrict__ out)
{
    __shared__ uint32_t As[2][KC * AS_V_ST];
    __shared__ uint32_t Bs[2][NTAP * KC * BS_STRIDE];

    const int g    = blockIdx.y;     // 0:(1,5)d1 1:(1,5)d2 2:(5,1)d1 3:(5,1)d2
    const bool vert = (g >= 2);
    const bool dil2 = (g & 1);
    const int tile = blockIdx.x;     // 128 tiles per image
    const int n = tile >> 7;
    int h0, w0 = 0;
    if (!vert) {
        h0 = tile & 127;                            // 1 row x 128 w
    } else {
        int r = tile & 127;
        h0 = (r >> 3) * 8;  w0 = (r & 7) * 16;      // 8 h x 16 w
    }
    const int AS_ST = vert ? AS_V_ST : AS_H_ST;

    const uint32_t* xb = g_xh + (size_t)n * 128 * IMG;   // [c2][pix]

    const int tid  = threadIdx.x;
    const int lane = tid & 31, warp = tid >> 5;
    const int wm = warp >> 1, wn = warp & 1;             // 4 M-warps x 2 N-warps
    const int qrow = lane >> 2, qcol = lane & 3;

    float acc[2][4][4];
    #pragma unroll
    for (int i = 0; i < 2; i++)
        #pragma unroll
        for (int j = 0; j < 4; j++)
            #pragma unroll
            for (int r = 0; r < 4; r++) acc[i][j][r] = 0.f;

    // A-fragment base offsets (m-rows qrow and qrow+8), warp tile M=32
    int offA[2][2];
    #pragma unroll
    for (int mt = 0; mt < 2; mt++) {
        #pragma unroll
        for (int hh = 0; hh < 2; hh++) {
            int mm = wm*32 + mt*16 + qrow + hh*8;   // 0..127
            offA[mt][hh] = vert ? (((mm >> 4) + 4) * 16 + (mm & 15))
                                : (4 + mm);
        }
    }

    const uint32_t asBase0 = (uint32_t)__cvta_generic_to_shared(&As[0][0]);
    const uint32_t asBase1 = (uint32_t)__cvta_generic_to_shared(&As[1][0]);
    const uint32_t bsBase0 = (uint32_t)__cvta_generic_to_shared(&Bs[0][0]);
    const uint32_t bsBase1 = (uint32_t)__cvta_generic_to_shared(&Bs[1][0]);

    // Pre-zero the horizontal w-halo in both buffers (128 writes)
    if (!vert && tid < 128) {
        int buf = tid >> 6, ch = (tid >> 3) & 7, j = tid & 7;
        As[buf][ch*AS_H_ST + (j < 4 ? j : 128 + j)] = 0u;
    }

    // issue cp.async copies for chunk q (16 channels = 8 k2-rows) into buffer `buf`
    auto issue = [&](int q, int buf) {
        const uint32_t aB = buf ? asBase1 : asBase0;
        const uint32_t bB = buf ? bsBase1 : bsBase0;
        const int k0 = q * KC;            // k2 base
        if (!vert) {
            // A: 8 k2 x 128 elems; thread -> (ch = tid>>5, u = tid&31), one 16B
            int ch = tid >> 5, u = tid & 31;
            const uint32_t* src = xb + (size_t)(k0 + ch) * IMG + h0 * HW + u * 4;
            uint32_t dst = aB + (ch*AS_H_ST + 4 + u*4) * 4;
            cp_async16(dst, src, 16);
        } else {
            // A: 8 k2 x 16 rows x 16 elems; thread -> (ch, rr, half), two 16B
            int ch = tid >> 5, rr = (tid & 31) >> 1, half = tid & 1;
            int row = h0 - 4 + rr;
            int ok = ((unsigned)row < (unsigned)HW) ? 16 : 0;
            int rowc = ok ? row : 0;
            const uint32_t* src = xb + (size_t)(k0 + ch) * IMG + rowc * HW + w0 + half*8;
            uint32_t dst = aB + (ch*AS_V_ST + rr*16 + half*8) * 4;
            cp_async16(dst,      src,     ok);
            cp_async16(dst + 16, src + 4, ok);
        }
        // B: 5 taps x 8 k2 x 64 co = 640 x 16B; strided over 256 threads
        #pragma unroll
        for (int i = 0; i < 3; i++) {
            int fi = tid + i*256;
            if (fi < 640) {
                int co4 = fi & 15, r = fi >> 4;       // r = t*8 + k
                int k = r & 7, t = r >> 3;
                const uint32_t* srcb =
                    g_wb + ((size_t)(g*NTAP + t) * 128 + k0 + k) * 64 + co4 * 4;
                uint32_t dst = bB + ((t*KC + k) * BS_STRIDE + co4*4) * 4;
                cp_async16(dst, srcb, 16);
            }
        }
        cp_commit();
    };

    issue(0, 0);
    for (int q = 0; q < NCHUNK; q++) {
        cp_wait0();
        __syncthreads();                 // chunk q visible; all warps past chunk q-1 MMAs
        if (q + 1 < NCHUNK) issue(q + 1, (q + 1) & 1);   // overlaps MMAs below

        const uint32_t* AsU = &As[q & 1][0];
        const uint32_t* BsU = &Bs[q & 1][0];
        #pragma unroll
        for (int t = 0; t < NTAP; t++) {
            int d  = dil2 ? (2*t - 4) : (t - 2);
            int sh = vert ? d * 16 : d;          // tap = pixel shift of A fragment
            uint32_t b0[4], b1[4];
            #pragma unroll
            for (int nt = 0; nt < 4; nt++) {
                int col = wn*32 + nt*8 + qrow;
                b0[nt] = BsU[(t*KC + qcol    ) * BS_STRIDE + col];
                b1[nt] = BsU[(t*KC + qcol + 4) * BS_STRIDE + col];
            }
            #pragma unroll
            for (int mt = 0; mt < 2; mt++) {
                uint32_t a0 = AsU[ qcol      * AS_ST + offA[mt][0] + sh];
                uint32_t a1 = AsU[ qcol      * AS_ST + offA[mt][1] + sh];
                uint32_t a2 = AsU[(qcol + 4) * AS_ST + offA[mt][0] + sh];
                uint32_t a3 = AsU[(qcol + 4) * AS_ST + offA[mt][1] + sh];
                #pragma unroll
                for (int nt = 0; nt < 4; nt++)
                    MMA_F16(acc[mt][nt], a0, a1, a2, a3, b0[nt], b1[nt]);
            }
        }
    }

    // Epilogue: bias + store
    const float* bias = (g==0) ? bb1 : (g==1) ? bb2 : (g==2) ? bb3 : bb4;
    float* ob = out + ((size_t)n * 256 + g * 64) * IMG;
    #pragma unroll
    for (int nt = 0; nt < 4; nt++) {
        #pragma unroll
        for (int r = 0; r < 4; r++) {
            int co = wn*32 + nt*8 + 2*qcol + (r & 1);
            float bv = bias[co];
            #pragma unroll
            for (int mt = 0; mt < 2; mt++) {
                int m = wm*32 + mt*16 + qrow + ((r >> 1) << 3);
                int pix = vert ? ((h0 + (m >> 4)) * HW + w0 + (m & 15))
                               : (h0 * HW + m);
                ob[(size_t)co * IMG + pix] = acc[mt][nt][r] + bv;
            }
        }
    }
}

extern "C" void kernel_launch(void* const* d_in, const int* in_sizes, int n_in,
                              void* d_out, int out_size) {
    const float* x  = (const float*)d_in[0];
    const float* w1 = (const float*)d_in[1];
    const float* b1 = (const float*)d_in[2];
    const float* w2 = (const float*)d_in[3];
    const float* b2 = (const float*)d_in[4];
    const float* w3 = (const float*)d_in[5];
    const float* b3 = (const float*)d_in[6];
    const float* w4 = (const float*)d_in[7];
    const float* b4 = (const float*)d_in[8];
    float* out = (float*)d_out;

    prep_weights<<<(NGROUP*NTAP*128*64 + 255)/256, 256>>>(w1, w2, w3, w4);
    convert_x<<<(int)(((size_t)16*128*IMG/4) / 256), 256>>>(x);
    dim3 grid(16 * 128, NGROUP);
    mrb_conv_kernel<<<grid, 256>>>(b1, b2, b3, b4, out);
}

// round 8
// speedup vs baseline: 1.0325x; 1.0325x over previous
#include <cuda_runtime.h>
#include <cuda_fp16.h>
#include <cstdint>
#include <cstddef>

#define C_IN 256
#define HW 128
#define IMG (HW*HW)
#define KC 8              // k2-rows (half2 channel-pairs) per chunk = 16 channels
#define NCHUNK 16
#define AS_H_ST 136       // elements: 4 halo + 128 + 4 halo  (% 32 == 8)
#define AS_V_ST 264       // elements: 16 rows x 16 w + pad    (% 32 == 8)
#define BROW 136          // B row stride in 32-bit words (per (t,kq) row); % 32 == 8
#define NTAP 5
#define NGROUP 4

// x converted to half2 channel-pairs: [img][c2(128)][pix]
__device__ uint32_t g_xh[(size_t)16*128*IMG];           // 128 MB
// binarized weights, PAIRED layout: [g][t][q(16)][kq(4)][co(64)][j(2)]
//   j=0 -> k2 = q*8+kq,  j=1 -> k2 = q*8+kq+4   (uint2-friendly)
__device__ uint32_t g_wb[NGROUP*NTAP*16*4*64*2];

__global__ void prep_weights(const float* __restrict__ w1, const float* __restrict__ w2,
                             const float* __restrict__ w3, const float* __restrict__ w4) {
    int idx = blockIdx.x * blockDim.x + threadIdx.x;     // pair index
    if (idx >= NGROUP*NTAP*16*4*64) return;
    int co = idx & 63;
    int kq = (idx >> 6) & 3;
    int q  = (idx >> 8) & 15;
    int gt = idx >> 12;              // g*5 + t
    int t = gt % 5, g = gt / 5;
    const float* w = g==0?w1:g==1?w2:g==2?w3:w4;
    #pragma unroll
    for (int j = 0; j < 2; j++) {
        int k2 = q*8 + kq + j*4;
        int c0 = 2*k2;
        float v0 = w[((size_t)co*C_IN + c0    )*NTAP + t];
        float v1 = w[((size_t)co*C_IN + c0 + 1)*NTAP + t];
        uint32_t lo = (v0 < 0.f) ? 0xBC00u : 0x3C00u;    // fp16 -1 / +1
        uint32_t hi = (v1 < 0.f) ? 0xBC00u : 0x3C00u;
        g_wb[idx*2 + j] = (hi << 16) | lo;
    }
}

__device__ __forceinline__ uint32_t pack_h2(float a, float b) {
    uint32_t r;
    asm("cvt.rn.f16x2.f32 %0, %1, %2;" : "=r"(r) : "f"(b), "f"(a));
    return r;
}

__global__ void convert_x(const float* __restrict__ x) {
    size_t i = (size_t)blockIdx.x * blockDim.x + threadIdx.x;   // uint4 index
    int pix4 = (int)(i & 4095);
    int c2   = (int)((i >> 12) & 127);
    int img  = (int)(i >> 19);
    const float4* p0 = reinterpret_cast<const float4*>(
        x + ((size_t)img*C_IN + 2*c2    )*IMG) + pix4;
    const float4* p1 = reinterpret_cast<const float4*>(
        x + ((size_t)img*C_IN + 2*c2 + 1)*IMG) + pix4;
    float4 a = *p0, b = *p1;
    uint4 o;
    o.x = pack_h2(a.x, b.x);
    o.y = pack_h2(a.y, b.y);
    o.z = pack_h2(a.z, b.z);
    o.w = pack_h2(a.w, b.w);
    reinterpret_cast<uint4*>(g_xh)[i] = o;
}

#define MMA_F16(cd, A0,A1,A2,A3, B0,B1)                                      \
  asm volatile("mma.sync.aligned.m16n8k16.row.col.f32.f16.f16.f32 "          \
    "{%0,%1,%2,%3},{%4,%5,%6,%7},{%8,%9},{%0,%1,%2,%3};\n"                   \
    : "+f"(cd[0]), "+f"(cd[1]), "+f"(cd[2]), "+f"(cd[3])                     \
    : "r"(A0), "r"(A1), "r"(A2), "r"(A3), "r"(B0), "r"(B1))

__device__ __forceinline__ void cp_async16(uint32_t dst, const void* src, int src_bytes) {
    asm volatile("cp.async.cg.shared.global [%0], [%1], 16, %2;\n"
                 :: "r"(dst), "l"(src), "r"(src_bytes));
}
__device__ __forceinline__ void cp_commit()  { asm volatile("cp.async.commit_group;\n"); }
__device__ __forceinline__ void cp_wait0()   { asm volatile("cp.async.wait_group 0;\n"); }

// CTA: M=128 pixels x N=64 co, fp16 MMA. 128 threads = 4 warps (2M x 2N),
// warp tile 64x32. Reg-capped to 128 -> 4 CTAs = 16 warps/SM.
__global__ __launch_bounds__(128, 4) void mrb_conv_kernel(
    const float* __restrict__ bb1, const float* __restrict__ bb2,
    const float* __restrict__ bb3, const float* __restrict__ bb4,
    float* __restrict__ out)
{
    __shared__ uint32_t As[2][KC * AS_V_ST];          // 2 x 8.25 KB
    __shared__ uint32_t Bs[2][NTAP * 4 * BROW];       // 2 x 10.625 KB

    const int g    = blockIdx.y;     // 0:(1,5)d1 1:(1,5)d2 2:(5,1)d1 3:(5,1)d2
    const bool vert = (g >= 2);
    const bool dil2 = (g & 1);
    const int tile = blockIdx.x;     // 128 tiles per image
    const int n = tile >> 7;
    int h0, w0 = 0;
    if (!vert) {
        h0 = tile & 127;                            // 1 row x 128 w
    } else {
        int r = tile & 127;
        h0 = (r >> 3) * 8;  w0 = (r & 7) * 16;      // 8 h x 16 w
    }
    const int AS_ST = vert ? AS_V_ST : AS_H_ST;

    const uint32_t* xb = g_xh + (size_t)n * 128 * IMG;   // [c2][pix]

    const int tid  = threadIdx.x;
    const int lane = tid & 31, warp = tid >> 5;
    const int wm = warp >> 1, wn = warp & 1;
    const int qrow = lane >> 2, qcol = lane & 3;

    float acc[4][4][4];
    #pragma unroll
    for (int i = 0; i < 4; i++)
        #pragma unroll
        for (int j = 0; j < 4; j++)
            #pragma unroll
            for (int r = 0; r < 4; r++) acc[i][j][r] = 0.f;

    // A-fragment base offsets within a k2 block (m-rows qrow and qrow+8)
    int offA[4][2];
    #pragma unroll
    for (int mt = 0; mt < 4; mt++) {
        #pragma unroll
        for (int hh = 0; hh < 2; hh++) {
            int mm = wm*64 + mt*16 + qrow + hh*8;   // 0..127
            offA[mt][hh] = vert ? (((mm >> 4) + 4) * 16 + (mm & 15))
                                : (4 + mm);
        }
    }

    const uint32_t asBase0 = (uint32_t)__cvta_generic_to_shared(&As[0][0]);
    const uint32_t asBase1 = (uint32_t)__cvta_generic_to_shared(&As[1][0]);
    const uint32_t bsBase0 = (uint32_t)__cvta_generic_to_shared(&Bs[0][0]);
    const uint32_t bsBase1 = (uint32_t)__cvta_generic_to_shared(&Bs[1][0]);

    // Pre-zero the horizontal w-halo in both buffers (128 writes)
    if (!vert) {
        int buf = tid >> 6, ch = (tid >> 3) & 7, j = tid & 7;
        As[buf][ch*AS_H_ST + (j < 4 ? j : 128 + j)] = 0u;
    }

    // issue cp.async copies for chunk q (16 channels = 8 k2-rows) into buffer `buf`
    auto issue = [&](int q, int buf) {
        const uint32_t aB = buf ? asBase1 : asBase0;
        const uint32_t bB = buf ? bsBase1 : bsBase0;
        const int k0 = q * KC;            // k2 base
        if (!vert) {
            // A: 8 k2 x 128 elems; thread -> (ch = tid>>4, s = tid&15), 8 elems
            int ch = tid >> 4, s = tid & 15;
            const uint32_t* src = xb + (size_t)(k0 + ch) * IMG + h0 * HW + s * 8;
            uint32_t dst = aB + (ch*AS_H_ST + 4 + s*8) * 4;
            cp_async16(dst,      src,     16);
            cp_async16(dst + 16, src + 4, 16);
        } else {
            // A: 8 k2 x 16 rows x 16 elems; thread -> (ch = tid>>4, row = tid&15)
            int ch = tid >> 4, rr = tid & 15;
            int row = h0 - 4 + rr;
            int ok = ((unsigned)row < (unsigned)HW) ? 16 : 0;
            int rowc = ok ? row : 0;
            const uint32_t* src = xb + (size_t)(k0 + ch) * IMG + rowc * HW + w0;
            uint32_t dst = aB + (ch*AS_V_ST + rr*16) * 4;
            #pragma unroll
            for (int j = 0; j < 4; j++)
                cp_async16(dst + j*16, src + j*4, ok);
        }
        // B paired: 5 t x 4 kq x 32 co-pairs, one 16B chunk (2 co x uint2) / thread / tap
        {
            int kq = tid >> 5, cp = tid & 31;
            #pragma unroll
            for (int t = 0; t < NTAP; t++) {
                const uint32_t* srcb =
                    g_wb + ((((size_t)(g*NTAP + t)*16 + q)*4 + kq)*64 + cp*2)*2;
                uint32_t dst = bB + ((t*4 + kq)*BROW + cp*4) * 4;
                cp_async16(dst, srcb, 16);
            }
        }
        cp_commit();
    };

    issue(0, 0);
    for (int q = 0; q < NCHUNK; q++) {
        cp_wait0();
        __syncthreads();                 // chunk q visible; all warps past chunk q-1 MMAs
        if (q + 1 < NCHUNK) issue(q + 1, (q + 1) & 1);   // overlaps MMAs below

        const uint32_t* AsU = &As[q & 1][0];
        const uint2*    BsP = reinterpret_cast<const uint2*>(&Bs[q & 1][0]);
        #pragma unroll
        for (int t = 0; t < NTAP; t++) {
            int d  = dil2 ? (2*t - 4) : (t - 2);
            int sh = vert ? d * 16 : d;          // tap = pixel shift of A fragment
            uint2 bp[4];
            #pragma unroll
            for (int nt = 0; nt < 4; nt++) {
                int col = wn*32 + nt*8 + qrow;
                bp[nt] = BsP[((size_t)(t*4 + qcol) * (BROW/2)) + col];
            }
            #pragma unroll
            for (int mt = 0; mt < 4; mt++) {
                uint32_t a0 = AsU[ qcol      * AS_ST + offA[mt][0] + sh];
                uint32_t a1 = AsU[ qcol      * AS_ST + offA[mt][1] + sh];
                uint32_t a2 = AsU[(qcol + 4) * AS_ST + offA[mt][0] + sh];
                uint32_t a3 = AsU[(qcol + 4) * AS_ST + offA[mt][1] + sh];
                #pragma unroll
                for (int nt = 0; nt < 4; nt++)
                    MMA_F16(acc[mt][nt], a0, a1, a2, a3, bp[nt].x, bp[nt].y);
            }
        }
    }

    // Epilogue: bias + store
    const float* bias = (g==0) ? bb1 : (g==1) ? bb2 : (g==2) ? bb3 : bb4;
    float* ob = out + ((size_t)n * 256 + g * 64) * IMG;
    #pragma unroll
    for (int nt = 0; nt < 4; nt++) {
        #pragma unroll
        for (int r = 0; r < 4; r++) {
            int co = wn*32 + nt*8 + 2*qcol + (r & 1);
            float bv = bias[co];
            #pragma unroll
            for (int mt = 0; mt < 4; mt++) {
                int m = wm*64 + mt*16 + qrow + ((r >> 1) << 3);
                int pix = vert ? ((h0 + (m >> 4)) * HW + w0 + (m & 15))
                               : (h0 * HW + m);
                ob[(size_t)co * IMG + pix] = acc[mt][nt][r] + bv;
            }
        }
    }
}

extern "C" void kernel_launch(void* const* d_in, const int* in_sizes, int n_in,
                              void* d_out, int out_size) {
    const float* x  = (const float*)d_in[0];
    const float* w1 = (const float*)d_in[1];
    const float* b1 = (const float*)d_in[2];
    const float* w2 = (const float*)d_in[3];
    const float* b2 = (const float*)d_in[4];
    const float* w3 = (const float*)d_in[5];
    const float* b3 = (const float*)d_in[6];
    const float* w4 = (const float*)d_in[7];
    const float* b4 = (const float*)d_in[8];
    float* out = (float*)d_out;

    prep_weights<<<(NGROUP*NTAP*16*4*64 + 255)/256, 256>>>(w1, w2, w3, w4);
    convert_x<<<(int)(((size_t)16*128*IMG/4) / 256), 256>>>(x);
    dim3 grid(16 * 128, NGROUP);
    mrb_conv_kernel<<<grid, 128>>>(b1, b2, b3, b4, out);
}

// round 9
// speedup vs baseline: 1.0424x; 1.0096x over previous
#include <cuda_runtime.h>
#include <cuda_fp16.h>
#include <cstdint>
#include <cstddef>

#define C_IN 256
#define HW 128
#define IMG (HW*HW)
#define KC 8              // k2-rows (half2 channel-pairs) per chunk = 16 channels
#define NCHUNK 16
#define NSTAGE 3
#define AS_H_ST 136       // elements: 4 halo + 128 + 4 halo  (% 32 == 8)
#define AS_V_ST 264       // elements: 16 rows x 16 w + pad    (% 32 == 8)
#define BS_STRIDE 72      // % 32 == 8
#define NTAP 5
#define NGROUP 4

#define AS_SZ (KC * AS_V_ST)            // 2112 words per stage
#define BS_SZ (NTAP * KC * BS_STRIDE)   // 2880 words per stage
#define SMEM_WORDS (NSTAGE * (AS_SZ + BS_SZ))
#define SMEM_BYTES (SMEM_WORDS * 4)     // 59904 B

// x converted to half2 channel-pairs: [img][c2(128)][pix]
__device__ uint32_t g_xh[(size_t)16*128*IMG];           // 128 MB
// binarized weights, half2 channel-pairs: [g][t][k2(128)][co(64)]
__device__ uint32_t g_wb[NGROUP*NTAP*128*64];

__global__ void prep_weights(const float* __restrict__ w1, const float* __restrict__ w2,
                             const float* __restrict__ w3, const float* __restrict__ w4) {
    int idx = blockIdx.x * blockDim.x + threadIdx.x;
    if (idx >= NGROUP*NTAP*128*64) return;
    int n   = idx & 63;
    int k2  = (idx >> 6) & 127;
    int gt  = idx >> 13;              // g*5 + t
    int t = gt % 5, g = gt / 5;
    int c0 = 2*k2;
    const float* w = g==0?w1:g==1?w2:g==2?w3:w4;
    float v0 = w[((size_t)n*C_IN + c0    )*NTAP + t];
    float v1 = w[((size_t)n*C_IN + c0 + 1)*NTAP + t];
    uint32_t lo = (v0 < 0.f) ? 0xBC00u : 0x3C00u;     // fp16 -1 / +1
    uint32_t hi = (v1 < 0.f) ? 0xBC00u : 0x3C00u;
    g_wb[idx] = (hi << 16) | lo;
}

__device__ __forceinline__ uint32_t pack_h2(float a, float b) {
    uint32_t r;
    asm("cvt.rn.f16x2.f32 %0, %1, %2;" : "=r"(r) : "f"(b), "f"(a));
    return r;
}

__global__ void convert_x(const float* __restrict__ x) {
    size_t i = (size_t)blockIdx.x * blockDim.x + threadIdx.x;   // uint4 index
    int pix4 = (int)(i & 4095);
    int c2   = (int)((i >> 12) & 127);
    int img  = (int)(i >> 19);
    const float4* p0 = reinterpret_cast<const float4*>(
        x + ((size_t)img*C_IN + 2*c2    )*IMG) + pix4;
    const float4* p1 = reinterpret_cast<const float4*>(
        x + ((size_t)img*C_IN + 2*c2 + 1)*IMG) + pix4;
    float4 a = *p0, b = *p1;
    uint4 o;
    o.x = pack_h2(a.x, b.x);
    o.y = pack_h2(a.y, b.y);
    o.z = pack_h2(a.z, b.z);
    o.w = pack_h2(a.w, b.w);
    reinterpret_cast<uint4*>(g_xh)[i] = o;
}

#define MMA_F16(cd, A0,A1,A2,A3, B0,B1)                                      \
  asm volatile("mma.sync.aligned.m16n8k16.row.col.f32.f16.f16.f32 "          \
    "{%0,%1,%2,%3},{%4,%5,%6,%7},{%8,%9},{%0,%1,%2,%3};\n"                   \
    : "+f"(cd[0]), "+f"(cd[1]), "+f"(cd[2]), "+f"(cd[3])                     \
    : "r"(A0), "r"(A1), "r"(A2), "r"(A3), "r"(B0), "r"(B1))

__device__ __forceinline__ void cp_async16(uint32_t dst, const void* src, int src_bytes) {
    asm volatile("cp.async.cg.shared.global [%0], [%1], 16, %2;\n"
                 :: "r"(dst), "l"(src), "r"(src_bytes));
}
__device__ __forceinline__ void cp_commit()  { asm volatile("cp.async.commit_group;\n"); }
__device__ __forceinline__ void cp_wait0()   { asm volatile("cp.async.wait_group 0;\n"); }
__device__ __forceinline__ void cp_wait1()   { asm volatile("cp.async.wait_group 1;\n"); }

// CTA: M=128 pixels x N=64 co, fp16 MMA. 128 threads = 4 warps (2M x 2N),
// warp tile 64x32. 3-stage cp.async ring (dynamic smem), 3 CTAs/SM.
__global__ __launch_bounds__(128, 3) void mrb_conv_kernel(
    const float* __restrict__ bb1, const float* __restrict__ bb2,
    const float* __restrict__ bb3, const float* __restrict__ bb4,
    float* __restrict__ out)
{
    extern __shared__ uint32_t dynsm[];      // [3 x AS_SZ][3 x BS_SZ]

    const int g    = blockIdx.y;     // 0:(1,5)d1 1:(1,5)d2 2:(5,1)d1 3:(5,1)d2
    const bool vert = (g >= 2);
    const bool dil2 = (g & 1);
    const int tile = blockIdx.x;     // 128 tiles per image
    const int n = tile >> 7;
    int h0, w0 = 0;
    if (!vert) {
        h0 = tile & 127;                            // 1 row x 128 w
    } else {
        int r = tile & 127;
        h0 = (r >> 3) * 8;  w0 = (r & 7) * 16;      // 8 h x 16 w
    }
    const int AS_ST = vert ? AS_V_ST : AS_H_ST;

    const uint32_t* xb = g_xh + (size_t)n * 128 * IMG;   // [c2][pix]

    const int tid  = threadIdx.x;
    const int lane = tid & 31, warp = tid >> 5;
    const int wm = warp >> 1, wn = warp & 1;
    const int qrow = lane >> 2, qcol = lane & 3;

    float acc[4][4][4];
    #pragma unroll
    for (int i = 0; i < 4; i++)
        #pragma unroll
        for (int j = 0; j < 4; j++)
            #pragma unroll
            for (int r = 0; r < 4; r++) acc[i][j][r] = 0.f;

    // A-fragment base offsets within a k2 block (m-rows qrow and qrow+8)
    int offA[4][2];
    #pragma unroll
    for (int mt = 0; mt < 4; mt++) {
        #pragma unroll
        for (int hh = 0; hh < 2; hh++) {
            int mm = wm*64 + mt*16 + qrow + hh*8;   // 0..127
            offA[mt][hh] = vert ? (((mm >> 4) + 4) * 16 + (mm & 15))
                                : (4 + mm);
        }
    }

    const uint32_t smBase = (uint32_t)__cvta_generic_to_shared(dynsm);

    // Pre-zero the horizontal w-halo in all 3 stages (never rewritten)
    if (!vert && tid < 64) {
        int ch = tid >> 3, j = tid & 7;
        int slot = ch*AS_H_ST + (j < 4 ? j : 128 + j);
        #pragma unroll
        for (int b = 0; b < NSTAGE; b++)
            dynsm[b*AS_SZ + slot] = 0u;
    }

    // issue cp.async copies for chunk q (16 channels = 8 k2-rows) into stage `buf`
    auto issue = [&](int q, int buf) {
        const uint32_t aB = smBase + (buf * AS_SZ) * 4;
        const uint32_t bB = smBase + (NSTAGE*AS_SZ + buf * BS_SZ) * 4;
        const int k0 = q * KC;            // k2 base
        if (!vert) {
            // A: 8 k2 x 128 elems; thread -> (ch = tid>>4, s = tid&15), 8 elems
            int ch = tid >> 4, s = tid & 15;
            const uint32_t* src = xb + (size_t)(k0 + ch) * IMG + h0 * HW + s * 8;
            uint32_t dst = aB + (ch*AS_H_ST + 4 + s*8) * 4;
            cp_async16(dst,      src,     16);
            cp_async16(dst + 16, src + 4, 16);
        } else {
            // A: 8 k2 x 16 rows x 16 elems; thread -> (ch = tid>>4, row = tid&15)
            int ch = tid >> 4, rr = tid & 15;
            int row = h0 - 4 + rr;
            int ok = ((unsigned)row < (unsigned)HW) ? 16 : 0;
            int rowc = ok ? row : 0;
            const uint32_t* src = xb + (size_t)(k0 + ch) * IMG + rowc * HW + w0;
            uint32_t dst = aB + (ch*AS_V_ST + rr*16) * 4;
            #pragma unroll
            for (int j = 0; j < 4; j++)
                cp_async16(dst + j*16, src + j*4, ok);
        }
        // B: 5 taps x 8 k2 x 64 co; thread -> (k = tid>>4, co4 = tid&15)
        {
            int k = tid >> 4, co4 = tid & 15;
            const uint32_t* srcb = g_wb + ((size_t)(g*NTAP) * 128 + k0 + k) * 64 + co4 * 4;
            #pragma unroll
            for (int t = 0; t < NTAP; t++) {
                uint32_t dst = bB + ((t*KC + k) * BS_STRIDE + co4*4) * 4;
                cp_async16(dst, srcb + (size_t)t * 128 * 64, 16);
            }
        }
        cp_commit();
    };

    issue(0, 0);
    issue(1, 1);
    int buf = 0;
    for (int q = 0; q < NCHUNK; q++) {
        if (q + 1 < NCHUNK) cp_wait1();   // chunk q landed; q+1 may still fly
        else                cp_wait0();
        __syncthreads();                  // all warps past compute(q-1); stage reusable
        if (q + 2 < NCHUNK) {
            int nb = buf + 2; if (nb >= NSTAGE) nb -= NSTAGE;
            issue(q + 2, nb);             // overlaps MMAs below by ~2 compute phases
        }

        const uint32_t* AsU = dynsm + buf * AS_SZ;
        const uint32_t* BsU = dynsm + NSTAGE*AS_SZ + buf * BS_SZ;
        #pragma unroll
        for (int t = 0; t < NTAP; t++) {
            int d  = dil2 ? (2*t - 4) : (t - 2);
            int sh = vert ? d * 16 : d;          // tap = pixel shift of A fragment
            uint32_t b0[4], b1[4];
            #pragma unroll
            for (int nt = 0; nt < 4; nt++) {
                int col = wn*32 + nt*8 + qrow;
                b0[nt] = BsU[(t*KC + qcol    ) * BS_STRIDE + col];
                b1[nt] = BsU[(t*KC + qcol + 4) * BS_STRIDE + col];
            }
            #pragma unroll
            for (int mt = 0; mt < 4; mt++) {
                uint32_t a0 = AsU[ qcol      * AS_ST + offA[mt][0] + sh];
                uint32_t a1 = AsU[ qcol      * AS_ST + offA[mt][1] + sh];
                uint32_t a2 = AsU[(qcol + 4) * AS_ST + offA[mt][0] + sh];
                uint32_t a3 = AsU[(qcol + 4) * AS_ST + offA[mt][1] + sh];
                #pragma unroll
                for (int nt = 0; nt < 4; nt++)
                    MMA_F16(acc[mt][nt], a0, a1, a2, a3, b0[nt], b1[nt]);
            }
        }
        if (++buf >= NSTAGE) buf = 0;
    }

    // Epilogue: bias + store
    const float* bias = (g==0) ? bb1 : (g==1) ? bb2 : (g==2) ? bb3 : bb4;
    float* ob = out + ((size_t)n * 256 + g * 64) * IMG;
    #pragma unroll
    for (int nt = 0; nt < 4; nt++) {
        #pragma unroll
        for (int r = 0; r < 4; r++) {
            int co = wn*32 + nt*8 + 2*qcol + (r & 1);
            float bv = bias[co];
            #pragma unroll
            for (int mt = 0; mt < 4; mt++) {
                int m = wm*64 + mt*16 + qrow + ((r >> 1) << 3);
                int pix = vert ? ((h0 + (m >> 4)) * HW + w0 + (m & 15))
                               : (h0 * HW + m);
                ob[(size_t)co * IMG + pix] = acc[mt][nt][r] + bv;
            }
        }
    }
}

extern "C" void kernel_launch(void* const* d_in, const int* in_sizes, int n_in,
                              void* d_out, int out_size) {
    const float* x  = (const float*)d_in[0];
    const float* w1 = (const float*)d_in[1];
    const float* b1 = (const float*)d_in[2];
    const float* w2 = (const float*)d_in[3];
    const float* b2 = (const float*)d_in[4];
    const float* w3 = (const float*)d_in[5];
    const float* b3 = (const float*)d_in[6];
    const float* w4 = (const float*)d_in[7];
    const float* b4 = (const float*)d_in[8];
    float* out = (float*)d_out;

    cudaFuncSetAttribute(mrb_conv_kernel,
                         cudaFuncAttributeMaxDynamicSharedMemorySize, SMEM_BYTES);

    prep_weights<<<(NGROUP*NTAP*128*64 + 255)/256, 256>>>(w1, w2, w3, w4);
    convert_x<<<(int)(((size_t)16*128*IMG/4) / 256), 256>>>(x);
    dim3 grid(16 * 128, NGROUP);
    mrb_conv_kernel<<<grid, 128, SMEM_BYTES>>>(b1, b2, b3, b4, out);
}